// round 1
// baseline (speedup 1.0000x reference)
#include <cuda_runtime.h>
#include <math.h>

#define BB 256
#define NN 180
#define CC 768
#define RR 192
#define MM (BB*NN)   // 46080

// ---------------- scratch (static device allocations) ----------------
__device__ float g_Wqk[CC * 2 * RR];   // [768, 384] packed Wq|Wk
__device__ float g_bqk[2 * RR];        // [384]
__device__ float g_QK[(size_t)MM * 2 * RR];    // [M, 384] Q|K
__device__ float g_S[(size_t)BB * NN * NN];    // scores -> A_comb (in place)
__device__ float g_Z[(size_t)MM * CC];         // A_comb @ x
__device__ float g_H[(size_t)MM * CC];         // pre-LN h

// ---------------- kernel 0: pack weights ----------------
__global__ void pack_w(const float* __restrict__ Wq, const float* __restrict__ bq,
                       const float* __restrict__ Wk, const float* __restrict__ bk) {
    int k = blockIdx.x;      // 768
    int t = threadIdx.x;     // 192
    g_Wqk[k * 384 + t]       = Wq[k * 192 + t];
    g_Wqk[k * 384 + 192 + t] = Wk[k * 192 + t];
    if (k == 0) { g_bqk[t] = bq[t]; g_bqk[192 + t] = bk[t]; }
}

// ---------------- 128x128x8 SGEMM body (8x8 per thread, 256 threads) ----------------
template<int NC, bool RELU_ADD>
__device__ __forceinline__ void sgemm_body(
    const float* __restrict__ A, const float* __restrict__ Bm,
    const float* __restrict__ bias, const float* __restrict__ resid,
    float* __restrict__ Cm, int K)
{
    __shared__ float As[8][128];
    __shared__ float Bs[8][128];
    int tid = threadIdx.x;
    int bm = blockIdx.y * 128, bn = blockIdx.x * 128;
    int tx = tid & 15, ty = tid >> 4;
    int aRow = tid >> 1,  aCol = (tid & 1) * 4;
    int bRow = tid >> 5,  bCol = (tid & 31) * 4;
    const float* Ap = A + (size_t)(bm + aRow) * K + aCol;
    const float* Bp = Bm + (size_t)bRow * NC + bn + bCol;

    float acc[8][8];
    #pragma unroll
    for (int i = 0; i < 8; i++)
        #pragma unroll
        for (int j = 0; j < 8; j++) acc[i][j] = 0.f;

    for (int k0 = 0; k0 < K; k0 += 8) {
        float4 av = *(const float4*)(Ap + k0);
        As[aCol + 0][aRow] = av.x;
        As[aCol + 1][aRow] = av.y;
        As[aCol + 2][aRow] = av.z;
        As[aCol + 3][aRow] = av.w;
        float4 bv = *(const float4*)(Bp + (size_t)k0 * NC);
        *(float4*)&Bs[bRow][bCol] = bv;
        __syncthreads();
        #pragma unroll
        for (int k = 0; k < 8; k++) {
            float a[8], b[8];
            #pragma unroll
            for (int i = 0; i < 4; i++) { a[i] = As[k][ty * 4 + i]; a[4 + i] = As[k][64 + ty * 4 + i]; }
            #pragma unroll
            for (int j = 0; j < 4; j++) { b[j] = Bs[k][tx * 4 + j]; b[4 + j] = Bs[k][64 + tx * 4 + j]; }
            #pragma unroll
            for (int i = 0; i < 8; i++)
                #pragma unroll
                for (int j = 0; j < 8; j++)
                    acc[i][j] += a[i] * b[j];
        }
        __syncthreads();
    }

    #pragma unroll
    for (int i = 0; i < 8; i++) {
        int r = bm + ((i < 4) ? ty * 4 + i : 64 + ty * 4 + i - 4);
        #pragma unroll
        for (int j = 0; j < 8; j++) {
            int c = bn + ((j < 4) ? tx * 4 + j : 64 + tx * 4 + j - 4);
            float v = acc[i][j] + bias[c];
            if (RELU_ADD) v = fmaxf(v, 0.f) + resid[(size_t)r * NC + c];
            Cm[(size_t)r * NC + c] = v;
        }
    }
}

// kernel 1: [M,768] @ [768,384] + bqk -> g_QK
__global__ void __launch_bounds__(256) sgemm_qk(const float* __restrict__ x) {
    sgemm_body<384, false>(x, g_Wqk, g_bqk, nullptr, g_QK, CC);
}

// kernel 4: h = x + relu(g_Z @ Wg + bg) -> g_H
__global__ void __launch_bounds__(256) sgemm_out(const float* __restrict__ Wg,
                                                 const float* __restrict__ bg,
                                                 const float* __restrict__ x) {
    sgemm_body<768, true>(g_Z, Wg, bg, x, g_H, CC);
}

// ---------------- kernel 2: scores = Q @ K^T / sqrt(R), batched ----------------
__global__ void __launch_bounds__(256) scores_kernel() {
    int b  = blockIdx.z;
    int bn = blockIdx.y * 64;   // n tile
    int bm = blockIdx.x * 64;   // m tile
    __shared__ float Qs[16][64];
    __shared__ float Ks[16][64];
    int tid = threadIdx.x;
    int tx = tid & 15, ty = tid >> 4;
    int lRow = tid >> 2;            // 0..63
    int lCol = (tid & 3) * 4;       // 0,4,8,12
    const float* base = g_QK + (size_t)b * NN * 384;

    float acc[4][4];
    #pragma unroll
    for (int i = 0; i < 4; i++)
        #pragma unroll
        for (int j = 0; j < 4; j++) acc[i][j] = 0.f;

    for (int k0 = 0; k0 < RR; k0 += 16) {
        int n = bn + lRow;
        float4 qv = make_float4(0.f, 0.f, 0.f, 0.f);
        if (n < NN) qv = *(const float4*)(base + (size_t)n * 384 + k0 + lCol);
        Qs[lCol + 0][lRow] = qv.x; Qs[lCol + 1][lRow] = qv.y;
        Qs[lCol + 2][lRow] = qv.z; Qs[lCol + 3][lRow] = qv.w;
        int m = bm + lRow;
        float4 kv = make_float4(0.f, 0.f, 0.f, 0.f);
        if (m < NN) kv = *(const float4*)(base + (size_t)m * 384 + 192 + k0 + lCol);
        Ks[lCol + 0][lRow] = kv.x; Ks[lCol + 1][lRow] = kv.y;
        Ks[lCol + 2][lRow] = kv.z; Ks[lCol + 3][lRow] = kv.w;
        __syncthreads();
        #pragma unroll
        for (int k = 0; k < 16; k++) {
            float a[4], c[4];
            #pragma unroll
            for (int i = 0; i < 4; i++) a[i] = Qs[k][ty * 4 + i];
            #pragma unroll
            for (int j = 0; j < 4; j++) c[j] = Ks[k][tx * 4 + j];
            #pragma unroll
            for (int i = 0; i < 4; i++)
                #pragma unroll
                for (int j = 0; j < 4; j++)
                    acc[i][j] += a[i] * c[j];
        }
        __syncthreads();
    }

    const float scale = 0.07216878364870323f;   // 1/sqrt(192)
    #pragma unroll
    for (int i = 0; i < 4; i++) {
        int n = bn + ty * 4 + i;
        #pragma unroll
        for (int j = 0; j < 4; j++) {
            int m = bm + tx * 4 + j;
            if (n < NN && m < NN)
                g_S[(size_t)(b * NN + n) * NN + m] = acc[i][j] * scale;
        }
    }
}

// ---------------- kernel: softmax + combine (in place on g_S) ----------------
__global__ void __launch_bounds__(192) softmax_combine(const float* __restrict__ alpha,
                                                       const float* __restrict__ A_phys) {
    int n = blockIdx.x, b = blockIdx.y, t = threadIdx.x;
    float* Srow = g_S + (size_t)(b * NN + n) * NN;
    float v = (t < NN) ? Srow[t] : -3.0e38f;
    __shared__ float red[6];

    float m = v;
    #pragma unroll
    for (int o = 16; o > 0; o >>= 1) m = fmaxf(m, __shfl_xor_sync(0xffffffff, m, o));
    if ((t & 31) == 0) red[t >> 5] = m;
    __syncthreads();
    float mx = red[0];
    #pragma unroll
    for (int w = 1; w < 6; w++) mx = fmaxf(mx, red[w]);

    float e = (t < NN) ? expf(v - mx) : 0.f;
    __syncthreads();
    float s = e;
    #pragma unroll
    for (int o = 16; o > 0; o >>= 1) s += __shfl_xor_sync(0xffffffff, s, o);
    if ((t & 31) == 0) red[t >> 5] = s;
    __syncthreads();
    float tot = 0.f;
    #pragma unroll
    for (int w = 0; w < 6; w++) tot += red[w];

    float a = 1.f / (1.f + expf(-alpha[0]));
    if (t < NN)
        Srow[t] = a * A_phys[n * NN + t] + (1.f - a) * (e / tot);
}

// ---------------- kernel 3: z = A_comb @ x (batched 180x768x180) ----------------
__global__ void __launch_bounds__(256) aggregate_kernel(const float* __restrict__ x) {
    int b  = blockIdx.z;
    int bn = blockIdx.y * 64;   // n tile (3)
    int bc = blockIdx.x * 64;   // c tile (12)
    __shared__ float As[16][64];   // A_comb^T [k][n]
    __shared__ float Bs[16][64];   // x [k][c]
    int tid = threadIdx.x;
    int tx = tid & 15, ty = tid >> 4;
    const float* Srow = g_S + (size_t)b * NN * NN;
    const float* xb   = x   + (size_t)b * NN * CC;

    float acc[4][4];
    #pragma unroll
    for (int i = 0; i < 4; i++)
        #pragma unroll
        for (int j = 0; j < 4; j++) acc[i][j] = 0.f;

    for (int k0 = 0; k0 < NN; k0 += 16) {
        // A tile: 64 n-rows x 16 k, scalar with guards (K=180 not multiple of 16)
        {
            int row = tid >> 2;
            #pragma unroll
            for (int u = 0; u < 4; u++) {
                int col = (tid & 3) * 4 + u;
                int n = bn + row, kk = k0 + col;
                float vv = 0.f;
                if (n < NN && kk < NN) vv = Srow[(size_t)n * NN + kk];
                As[col][row] = vv;
            }
        }
        // B tile: 16 k-rows x 64 c, float4
        {
            int row = tid >> 4, col = (tid & 15) * 4;
            int kk = k0 + row;
            float4 bv = make_float4(0.f, 0.f, 0.f, 0.f);
            if (kk < NN) bv = *(const float4*)(xb + (size_t)kk * CC + bc + col);
            *(float4*)&Bs[row][col] = bv;
        }
        __syncthreads();
        #pragma unroll
        for (int k = 0; k < 16; k++) {
            float a[4], c[4];
            #pragma unroll
            for (int i = 0; i < 4; i++) a[i] = As[k][ty * 4 + i];
            #pragma unroll
            for (int j = 0; j < 4; j++) c[j] = Bs[k][tx * 4 + j];
            #pragma unroll
            for (int i = 0; i < 4; i++)
                #pragma unroll
                for (int j = 0; j < 4; j++)
                    acc[i][j] += a[i] * c[j];
        }
        __syncthreads();
    }

    #pragma unroll
    for (int i = 0; i < 4; i++) {
        int n = bn + ty * 4 + i;
        if (n < NN) {
            #pragma unroll
            for (int j = 0; j < 4; j++)
                g_Z[((size_t)b * NN + n) * CC + bc + tx * 4 + j] = acc[i][j];
        }
    }
}

// ---------------- kernel 5: LayerNorm ----------------
__global__ void __launch_bounds__(256) ln_kernel(const float* __restrict__ gamma,
                                                 const float* __restrict__ beta,
                                                 float* __restrict__ out) {
    int row = blockIdx.x;
    int t = threadIdx.x;
    const float* h = g_H + (size_t)row * CC;
    float v0 = h[t], v1 = h[t + 256], v2 = h[t + 512];
    float s  = v0 + v1 + v2;
    float sq = v0 * v0 + v1 * v1 + v2 * v2;

    __shared__ float r1[8], r2[8];
    #pragma unroll
    for (int o = 16; o > 0; o >>= 1) {
        s  += __shfl_xor_sync(0xffffffff, s, o);
        sq += __shfl_xor_sync(0xffffffff, sq, o);
    }
    if ((t & 31) == 0) { r1[t >> 5] = s; r2[t >> 5] = sq; }
    __syncthreads();
    float ts = 0.f, tq = 0.f;
    #pragma unroll
    for (int w = 0; w < 8; w++) { ts += r1[w]; tq += r2[w]; }

    float mu  = ts * (1.f / 768.f);
    float var = tq * (1.f / 768.f) - mu * mu;
    float inv = rsqrtf(var + 1e-5f);
    float* o = out + (size_t)row * CC;
    o[t]       = (v0 - mu) * inv * gamma[t]       + beta[t];
    o[t + 256] = (v1 - mu) * inv * gamma[t + 256] + beta[t + 256];
    o[t + 512] = (v2 - mu) * inv * gamma[t + 512] + beta[t + 512];
}

// ---------------- host launcher ----------------
extern "C" void kernel_launch(void* const* d_in, const int* in_sizes, int n_in,
                              void* d_out, int out_size) {
    const float* x     = (const float*)d_in[0];
    const float* Wq    = (const float*)d_in[1];
    const float* bq    = (const float*)d_in[2];
    const float* Wk    = (const float*)d_in[3];
    const float* bk    = (const float*)d_in[4];
    const float* Wg    = (const float*)d_in[5];
    const float* bg    = (const float*)d_in[6];
    const float* gamma = (const float*)d_in[7];
    const float* beta  = (const float*)d_in[8];
    const float* alpha = (const float*)d_in[9];
    const float* A_phys= (const float*)d_in[10];
    float* out = (float*)d_out;

    pack_w<<<CC, 192>>>(Wq, bq, Wk, bk);
    sgemm_qk<<<dim3(384 / 128, MM / 128), 256>>>(x);               // (3, 360)
    scores_kernel<<<dim3(3, 3, BB), 256>>>();
    softmax_combine<<<dim3(NN, BB), 192>>>(alpha, A_phys);
    aggregate_kernel<<<dim3(CC / 64, 3, BB), 256>>>(x);            // (12, 3, 256)
    sgemm_out<<<dim3(CC / 128, MM / 128), 256>>>(Wg, bg, x);       // (6, 360)
    ln_kernel<<<MM, 256>>>(gamma, beta, out);
}

// round 3
// speedup vs baseline: 1.9631x; 1.9631x over previous
#include <cuda_runtime.h>
#include <math.h>
#include <stdint.h>

#define BB 256
#define NN 180
#define CC 768
#define RR 192
#define MM (BB*NN)     // 46080
#define NCHUNK (CC/32) // 24 K-chunks of 32 floats

// ---------------- scratch (static device allocations) ----------------
__device__ float g_Wqkt[384 * 768];          // [n][k] tf32-rounded, Wq^T | Wk^T
__device__ float g_Wgt[768 * 768];           // [n][k] tf32-rounded Wg^T
__device__ float g_bqk[384];
__device__ float g_QK[(size_t)MM * 384];     // [M, 384] Q|K
__device__ float g_S[(size_t)BB * NN * NN];  // scores -> A_comb (in place)
__device__ float g_Z[(size_t)MM * CC];       // A_comb @ x
__device__ float g_H[(size_t)MM * CC];       // pre-LN h

// ---------------- helpers ----------------
__device__ __forceinline__ uint32_t smem_u32(const void* p) {
    uint32_t a;
    asm("{ .reg .u64 t; cvta.to.shared.u64 t, %1; cvt.u32.u64 %0, t; }" : "=r"(a) : "l"(p));
    return a;
}
__device__ __forceinline__ uint32_t cvt_tf32(float f) {
    uint32_t r;
    asm("cvt.rna.tf32.f32 %0, %1;" : "=r"(r) : "f"(f));
    return r;
}
// 128-byte swizzle on byte offsets (rows are 128B = 32 floats)
#define SWZB(o) ((o) ^ (((o) >> 3) & 0x70))
// swizzled float index for (row, float-col) in a [128][32] tile
__device__ __forceinline__ int swzf(int r, int kf) {
    return SWZB(r * 128 + kf * 4) >> 2;
}

__device__ __forceinline__ void cp16(uint32_t dst, const void* src) {
    asm volatile("cp.async.ca.shared.global [%0], [%1], 16;"
                 :: "r"(dst), "l"(src) : "memory");
}
#define CP_COMMIT() asm volatile("cp.async.commit_group;" ::: "memory")
#define CP_WAIT1()  asm volatile("cp.async.wait_group 1;" ::: "memory")
#define CP_WAIT0()  asm volatile("cp.async.wait_group 0;" ::: "memory")

__device__ __forceinline__ void mma_tf32(float* c, const uint32_t* a, const uint32_t* b) {
    asm volatile(
        "mma.sync.aligned.m16n8k8.row.col.f32.tf32.tf32.f32 "
        "{%0,%1,%2,%3}, {%4,%5,%6,%7}, {%8,%9}, {%0,%1,%2,%3};"
        : "+f"(c[0]), "+f"(c[1]), "+f"(c[2]), "+f"(c[3])
        : "r"(a[0]), "r"(a[1]), "r"(a[2]), "r"(a[3]), "r"(b[0]), "r"(b[1]));
}

// ---------------- tf32 mma.sync GEMM: Out[M,NC] = A[M,768] @ Wt[NC,768]^T ----------------
// Tile 128x128x32, 256 threads (8 warps as 4m x 2n), 2-stage cp.async pipeline.
template<int NC, bool RELU>
__global__ void __launch_bounds__(256, 2) gemm_mma(
    const float* __restrict__ A,      // [M, 768] fp32 (consumed as tf32-truncated)
    const float* __restrict__ Wt,     // [NC, 768] tf32 (RNA-rounded bit patterns)
    const float* __restrict__ bias,   // [NC]
    const float* __restrict__ resid,  // [M, NC] (RELU path)
    float* __restrict__ Out)          // [M, NC]
{
    extern __shared__ float sm[];     // 2 buffers x (A 4096 floats + B 4096 floats)
    const uint32_t sbase = smem_u32(sm);
    const int tid  = threadIdx.x;
    const int wid  = tid >> 5;
    const int lane = tid & 31;
    const int wm   = wid & 3;         // 4 warps over m (32 rows each)
    const int wn   = wid >> 2;        // 2 warps over n (64 cols each)
    const int lr   = lane >> 2;
    const int lc   = lane & 3;
    const int bm   = blockIdx.y * 128;
    const int bn   = blockIdx.x * 128;

    float acc[2][8][4];
    #pragma unroll
    for (int i = 0; i < 2; i++)
        #pragma unroll
        for (int j = 0; j < 8; j++)
            #pragma unroll
            for (int k = 0; k < 4; k++) acc[i][j][k] = 0.f;

    const int ldrow = tid >> 3;       // 0..31 (+i*32)
    const int ldc4  = tid & 7;        // 16B unit within 128B row

    auto issue_load = [&](int c, int b) {
        const uint32_t abase = sbase + b * 32768u;   // bytes
        const uint32_t bbase = abase + 16384u;
        const int k0 = c * 32;
        #pragma unroll
        for (int i = 0; i < 4; i++) {
            const int row = ldrow + i * 32;
            const uint32_t soff = SWZB(row * 128 + ldc4 * 16);
            cp16(abase + soff, A  + (size_t)(bm + row) * CC + k0 + ldc4 * 4);
            cp16(bbase + soff, Wt + (size_t)(bn + row) * CC + k0 + ldc4 * 4);
        }
        CP_COMMIT();
    };

    issue_load(0, 0);

    for (int c = 0; c < NCHUNK; c++) {
        if (c + 1 < NCHUNK) { issue_load(c + 1, (c + 1) & 1); CP_WAIT1(); }
        else                { CP_WAIT0(); }
        __syncthreads();

        const float* As = sm + (c & 1) * 8192;
        const float* Bs = As + 4096;

        #pragma unroll
        for (int ks = 0; ks < 4; ks++) {
            const int k0f = ks * 8;
            uint32_t afr[2][4];
            #pragma unroll
            for (int fm = 0; fm < 2; fm++) {
                const int r = wm * 32 + fm * 16 + lr;
                afr[fm][0] = __float_as_uint(As[swzf(r,     k0f + lc)]);
                afr[fm][1] = __float_as_uint(As[swzf(r + 8, k0f + lc)]);
                afr[fm][2] = __float_as_uint(As[swzf(r,     k0f + lc + 4)]);
                afr[fm][3] = __float_as_uint(As[swzf(r + 8, k0f + lc + 4)]);
            }
            uint32_t bfr[8][2];
            #pragma unroll
            for (int fn = 0; fn < 8; fn++) {
                const int n = wn * 64 + fn * 8 + lr;
                bfr[fn][0] = __float_as_uint(Bs[swzf(n, k0f + lc)]);
                bfr[fn][1] = __float_as_uint(Bs[swzf(n, k0f + lc + 4)]);
            }
            #pragma unroll
            for (int fm = 0; fm < 2; fm++)
                #pragma unroll
                for (int fn = 0; fn < 8; fn++)
                    mma_tf32(acc[fm][fn], afr[fm], bfr[fn]);
        }
        __syncthreads();
    }

    // ---- epilogue ----
    #pragma unroll
    for (int fm = 0; fm < 2; fm++) {
        #pragma unroll
        for (int h = 0; h < 2; h++) {
            const int m = bm + wm * 32 + fm * 16 + lr + h * 8;
            #pragma unroll
            for (int fn = 0; fn < 8; fn++) {
                const int n = bn + wn * 64 + fn * 8 + lc * 2;
                float vx = acc[fm][fn][h * 2 + 0] + bias[n];
                float vy = acc[fm][fn][h * 2 + 1] + bias[n + 1];
                if (RELU) {
                    const float2 rx = *(const float2*)(resid + (size_t)m * NC + n);
                    vx = fmaxf(vx, 0.f) + rx.x;
                    vy = fmaxf(vy, 0.f) + rx.y;
                }
                *(float2*)(Out + (size_t)m * NC + n) = make_float2(vx, vy);
            }
        }
    }
}

// ---------------- pack kernels: transpose weights to [N,K], round to tf32 ----------------
__global__ void pack_wqk(const float* __restrict__ Wq, const float* __restrict__ Wk) {
    __shared__ float t[32][33];
    int k0 = blockIdx.x * 32, n0 = blockIdx.y * 32, z = blockIdx.z;
    const float* W = z ? Wk : Wq;
    int tx = threadIdx.x, ty = threadIdx.y;
    t[ty][tx] = W[(size_t)(k0 + ty) * RR + n0 + tx];
    __syncthreads();
    g_Wqkt[(size_t)(z * RR + n0 + ty) * CC + k0 + tx] = __uint_as_float(cvt_tf32(t[tx][ty]));
}

__global__ void pack_wg(const float* __restrict__ Wg) {
    __shared__ float t[32][33];
    int k0 = blockIdx.x * 32, n0 = blockIdx.y * 32;
    int tx = threadIdx.x, ty = threadIdx.y;
    t[ty][tx] = Wg[(size_t)(k0 + ty) * CC + n0 + tx];
    __syncthreads();
    g_Wgt[(size_t)(n0 + ty) * CC + k0 + tx] = __uint_as_float(cvt_tf32(t[tx][ty]));
}

__global__ void pack_bias(const float* __restrict__ bq, const float* __restrict__ bk) {
    int t = threadIdx.x;
    g_bqk[t] = (t < RR) ? bq[t] : bk[t - RR];
}

// ---------------- scores = Q @ K^T / sqrt(R), batched (SIMT) ----------------
__global__ void __launch_bounds__(256) scores_kernel() {
    int b  = blockIdx.z;
    int bn = blockIdx.y * 64;
    int bm = blockIdx.x * 64;
    __shared__ float Qs[16][64];
    __shared__ float Ks[16][64];
    int tid = threadIdx.x;
    int tx = tid & 15, ty = tid >> 4;
    int lRow = tid >> 2;
    int lCol = (tid & 3) * 4;
    const float* base = g_QK + (size_t)b * NN * 384;

    float acc[4][4];
    #pragma unroll
    for (int i = 0; i < 4; i++)
        #pragma unroll
        for (int j = 0; j < 4; j++) acc[i][j] = 0.f;

    for (int k0 = 0; k0 < RR; k0 += 16) {
        int n = bn + lRow;
        float4 qv = make_float4(0.f, 0.f, 0.f, 0.f);
        if (n < NN) qv = *(const float4*)(base + (size_t)n * 384 + k0 + lCol);
        Qs[lCol + 0][lRow] = qv.x; Qs[lCol + 1][lRow] = qv.y;
        Qs[lCol + 2][lRow] = qv.z; Qs[lCol + 3][lRow] = qv.w;
        int m = bm + lRow;
        float4 kv = make_float4(0.f, 0.f, 0.f, 0.f);
        if (m < NN) kv = *(const float4*)(base + (size_t)m * 384 + 192 + k0 + lCol);
        Ks[lCol + 0][lRow] = kv.x; Ks[lCol + 1][lRow] = kv.y;
        Ks[lCol + 2][lRow] = kv.z; Ks[lCol + 3][lRow] = kv.w;
        __syncthreads();
        #pragma unroll
        for (int k = 0; k < 16; k++) {
            float a[4], c[4];
            #pragma unroll
            for (int i = 0; i < 4; i++) a[i] = Qs[k][ty * 4 + i];
            #pragma unroll
            for (int j = 0; j < 4; j++) c[j] = Ks[k][tx * 4 + j];
            #pragma unroll
            for (int i = 0; i < 4; i++)
                #pragma unroll
                for (int j = 0; j < 4; j++)
                    acc[i][j] += a[i] * c[j];
        }
        __syncthreads();
    }

    const float scale = 0.07216878364870323f;   // 1/sqrt(192)
    #pragma unroll
    for (int i = 0; i < 4; i++) {
        int n = bn + ty * 4 + i;
        #pragma unroll
        for (int j = 0; j < 4; j++) {
            int m = bm + tx * 4 + j;
            if (n < NN && m < NN)
                g_S[(size_t)(b * NN + n) * NN + m] = acc[i][j] * scale;
        }
    }
}

// ---------------- softmax + combine (in place on g_S) ----------------
__global__ void __launch_bounds__(192) softmax_combine(const float* __restrict__ alpha,
                                                       const float* __restrict__ A_phys) {
    int n = blockIdx.x, b = blockIdx.y, t = threadIdx.x;
    float* Srow = g_S + (size_t)(b * NN + n) * NN;
    float v = (t < NN) ? Srow[t] : -3.0e38f;
    __shared__ float red[6];

    float m = v;
    #pragma unroll
    for (int o = 16; o > 0; o >>= 1) m = fmaxf(m, __shfl_xor_sync(0xffffffff, m, o));
    if ((t & 31) == 0) red[t >> 5] = m;
    __syncthreads();
    float mx = red[0];
    #pragma unroll
    for (int w = 1; w < 6; w++) mx = fmaxf(mx, red[w]);

    float e = (t < NN) ? expf(v - mx) : 0.f;
    __syncthreads();
    float s = e;
    #pragma unroll
    for (int o = 16; o > 0; o >>= 1) s += __shfl_xor_sync(0xffffffff, s, o);
    if ((t & 31) == 0) red[t >> 5] = s;
    __syncthreads();
    float tot = 0.f;
    #pragma unroll
    for (int w = 0; w < 6; w++) tot += red[w];

    float a = 1.f / (1.f + expf(-alpha[0]));
    if (t < NN)
        Srow[t] = a * A_phys[n * NN + t] + (1.f - a) * (e / tot);
}

// ---------------- z = A_comb @ x (batched, SIMT) ----------------
__global__ void __launch_bounds__(256) aggregate_kernel(const float* __restrict__ x) {
    int b  = blockIdx.z;
    int bn = blockIdx.y * 64;
    int bc = blockIdx.x * 64;
    __shared__ float As[16][64];
    __shared__ float Bs[16][64];
    int tid = threadIdx.x;
    int tx = tid & 15, ty = tid >> 4;
    const float* Srow = g_S + (size_t)b * NN * NN;
    const float* xb   = x   + (size_t)b * NN * CC;

    float acc[4][4];
    #pragma unroll
    for (int i = 0; i < 4; i++)
        #pragma unroll
        for (int j = 0; j < 4; j++) acc[i][j] = 0.f;

    for (int k0 = 0; k0 < NN; k0 += 16) {
        {
            int row = tid >> 2;
            #pragma unroll
            for (int u = 0; u < 4; u++) {
                int col = (tid & 3) * 4 + u;
                int n = bn + row, kk = k0 + col;
                float vv = 0.f;
                if (n < NN && kk < NN) vv = Srow[(size_t)n * NN + kk];
                As[col][row] = vv;
            }
        }
        {
            int row = tid >> 4, col = (tid & 15) * 4;
            int kk = k0 + row;
            float4 bv = make_float4(0.f, 0.f, 0.f, 0.f);
            if (kk < NN) bv = *(const float4*)(xb + (size_t)kk * CC + bc + col);
            *(float4*)&Bs[row][col] = bv;
        }
        __syncthreads();
        #pragma unroll
        for (int k = 0; k < 16; k++) {
            float a[4], c[4];
            #pragma unroll
            for (int i = 0; i < 4; i++) a[i] = As[k][ty * 4 + i];
            #pragma unroll
            for (int j = 0; j < 4; j++) c[j] = Bs[k][tx * 4 + j];
            #pragma unroll
            for (int i = 0; i < 4; i++)
                #pragma unroll
                for (int j = 0; j < 4; j++)
                    acc[i][j] += a[i] * c[j];
        }
        __syncthreads();
    }

    #pragma unroll
    for (int i = 0; i < 4; i++) {
        int n = bn + ty * 4 + i;
        if (n < NN) {
            #pragma unroll
            for (int j = 0; j < 4; j++)
                g_Z[((size_t)b * NN + n) * CC + bc + tx * 4 + j] = acc[i][j];
        }
    }
}

// ---------------- LayerNorm ----------------
__global__ void __launch_bounds__(256) ln_kernel(const float* __restrict__ gamma,
                                                 const float* __restrict__ beta,
                                                 float* __restrict__ out) {
    int row = blockIdx.x;
    int t = threadIdx.x;
    const float* h = g_H + (size_t)row * CC;
    float v0 = h[t], v1 = h[t + 256], v2 = h[t + 512];
    float s  = v0 + v1 + v2;
    float sq = v0 * v0 + v1 * v1 + v2 * v2;

    __shared__ float r1[8], r2[8];
    #pragma unroll
    for (int o = 16; o > 0; o >>= 1) {
        s  += __shfl_xor_sync(0xffffffff, s, o);
        sq += __shfl_xor_sync(0xffffffff, sq, o);
    }
    if ((t & 31) == 0) { r1[t >> 5] = s; r2[t >> 5] = sq; }
    __syncthreads();
    float ts = 0.f, tq = 0.f;
    #pragma unroll
    for (int w = 0; w < 8; w++) { ts += r1[w]; tq += r2[w]; }

    float mu  = ts * (1.f / 768.f);
    float var = tq * (1.f / 768.f) - mu * mu;
    float inv = rsqrtf(var + 1e-5f);
    float* o = out + (size_t)row * CC;
    o[t]       = (v0 - mu) * inv * gamma[t]       + beta[t];
    o[t + 256] = (v1 - mu) * inv * gamma[t + 256] + beta[t + 256];
    o[t + 512] = (v2 - mu) * inv * gamma[t + 512] + beta[t + 512];
}

// ---------------- host launcher ----------------
#define GEMM_SMEM 65536

extern "C" void kernel_launch(void* const* d_in, const int* in_sizes, int n_in,
                              void* d_out, int out_size) {
    const float* x     = (const float*)d_in[0];
    const float* Wq    = (const float*)d_in[1];
    const float* bq    = (const float*)d_in[2];
    const float* Wk    = (const float*)d_in[3];
    const float* bk    = (const float*)d_in[4];
    const float* Wg    = (const float*)d_in[5];
    const float* bg    = (const float*)d_in[6];
    const float* gamma = (const float*)d_in[7];
    const float* beta  = (const float*)d_in[8];
    const float* alpha = (const float*)d_in[9];
    const float* A_phys= (const float*)d_in[10];
    float* out = (float*)d_out;

    cudaFuncSetAttribute(gemm_mma<384, false>, cudaFuncAttributeMaxDynamicSharedMemorySize, GEMM_SMEM);
    cudaFuncSetAttribute(gemm_mma<768, true>,  cudaFuncAttributeMaxDynamicSharedMemorySize, GEMM_SMEM);

    void *wqkt, *wgt, *bqk_, *qk, *z_, *h_;
    cudaGetSymbolAddress(&wqkt, g_Wqkt);
    cudaGetSymbolAddress(&wgt,  g_Wgt);
    cudaGetSymbolAddress(&bqk_, g_bqk);
    cudaGetSymbolAddress(&qk,   g_QK);
    cudaGetSymbolAddress(&z_,   g_Z);
    cudaGetSymbolAddress(&h_,   g_H);

    dim3 b32(32, 32);
    pack_wqk<<<dim3(24, 6, 2), b32>>>(Wq, Wk);
    pack_wg<<<dim3(24, 24), b32>>>(Wg);
    pack_bias<<<1, 384>>>(bq, bk);

    gemm_mma<384, false><<<dim3(3, 360), 256, GEMM_SMEM>>>(
        x, (const float*)wqkt, (const float*)bqk_, nullptr, (float*)qk);
    scores_kernel<<<dim3(3, 3, BB), 256>>>();
    softmax_combine<<<dim3(NN, BB), 192>>>(alpha, A_phys);
    aggregate_kernel<<<dim3(CC / 64, 3, BB), 256>>>(x);
    gemm_mma<768, true><<<dim3(6, 360), 256, GEMM_SMEM>>>(
        (const float*)z_, (const float*)wgt, bg, x, (float*)h_);
    ln_kernel<<<MM, 256>>>(gamma, beta, out);
}